// round 1
// baseline (speedup 1.0000x reference)
#include <cuda_runtime.h>

// Problem constants (fixed shapes from reference setup_inputs)
#define CIN   128
#define HH    32
#define WW    32
#define BB    16
#define COUT  256
#define DTOT  1152          // CIN * 3 * 3
#define RCH   18            // DTOT / 64 chunks (exact, no padding)
#define NPIX  16384         // BB * HH * WW

#define NT    128           // pixel tile per CTA
#define KT    32            // k-slab per SMEM phase
#define NTHREADS 512

// Scratch: quantized transposed weights [d][m] and encoded min/max
__device__ float    g_wq[DTOT * COUT];
__device__ unsigned g_mm[2];   // [0] = enc(max w), [1] = enc(max -w)

__device__ __forceinline__ unsigned encf(float f) {
    int b = __float_as_int(f);
    return (b < 0) ? ~(unsigned)b : ((unsigned)b | 0x80000000u);
}
__device__ __forceinline__ float decf(unsigned u) {
    int b = (u & 0x80000000u) ? (int)(u & 0x7fffffffu) : ~(int)u;
    return __int_as_float(b);
}

__global__ void k_init_mm() {
    if (threadIdx.x < 2) g_mm[threadIdx.x] = 0u;
}

__global__ void k_minmax(const float* __restrict__ w, int n) {
    unsigned mx = 0u, mn = 0u;
    for (int i = blockIdx.x * blockDim.x + threadIdx.x; i < n;
         i += gridDim.x * blockDim.x) {
        float f = w[i];
        unsigned e0 = encf(f), e1 = encf(-f);
        mx = mx > e0 ? mx : e0;
        mn = mn > e1 ? mn : e1;
    }
    #pragma unroll
    for (int o = 16; o; o >>= 1) {
        unsigned a = __shfl_xor_sync(0xffffffffu, mx, o);
        unsigned b = __shfl_xor_sync(0xffffffffu, mn, o);
        mx = mx > a ? mx : a;
        mn = mn > b ? mn : b;
    }
    if ((threadIdx.x & 31) == 0) {
        atomicMax(&g_mm[0], mx);
        atomicMax(&g_mm[1], mn);
    }
}

// Quantize (round-half-even + clamp to [-7,7]) and transpose to [d][m]
__global__ void k_quant(const float* __restrict__ w) {
    int idx = blockIdx.x * blockDim.x + threadIdx.x;  // over COUT*DTOT
    if (idx >= COUT * DTOT) return;
    float mx = decf(g_mm[0]);
    float mn = -decf(g_mm[1]);
    float scale = 15.0f / (mx - mn + 1e-9f);
    int m = idx / DTOT;
    int d = idx - m * DTOT;
    float q = rintf(w[idx] * scale);
    q = fminf(fmaxf(q, -7.0f), 7.0f);
    g_wq[d * COUT + m] = q;
}

// Main kernel: CTA = [256 channels x 128 pixels], 18 chunks of K=64.
// Thread tile 8 ch x 8 pix as f32x2 accumulators; sign-count per chunk.
__global__ __launch_bounds__(NTHREADS, 1)
void k_onn_main(const float* __restrict__ inp, float* __restrict__ out) {
    __shared__ float ws_s[KT][COUT];   // 32 KB, k-major weights
    __shared__ float xs_s[KT][NT];     // 16 KB, k-major im2col x

    const int tid = threadIdx.x;
    const int ty  = tid >> 4;          // 0..31 -> channel group (ty*8)
    const int tx  = tid & 15;          // 0..15 -> pixel group  (tx*8)
    const int nb  = blockIdx.x;        // 0..127
    const int b   = nb >> 3;                 // batch
    const int pixbase = (nb & 7) * NT;       // 0..896 within image
    const int y0  = pixbase >> 5;            // starting image row

    const float* __restrict__ inb = inp + b * (CIN * HH * WW);

    unsigned cnt[8][2];
    #pragma unroll
    for (int i = 0; i < 8; i++) { cnt[i][0] = 0u; cnt[i][1] = 0u; }

    for (int r = 0; r < RCH; r++) {
        unsigned long long acc[8][4];
        #pragma unroll
        for (int i = 0; i < 8; i++)
            #pragma unroll
            for (int j = 0; j < 4; j++) acc[i][j] = 0ull;

        #pragma unroll 1
        for (int half = 0; half < 2; half++) {
            const int dbase = r * 64 + half * KT;
            __syncthreads();  // previous compute done before overwriting SMEM

            // ---- load weights slab: KT x COUT floats = 2048 float4 ----
            #pragma unroll
            for (int t = 0; t < 4; t++) {
                int idx = tid + t * NTHREADS;     // 0..2047
                int k   = idx >> 6;               // 64 float4 per k-row
                int mq  = idx & 63;
                *(float4*)&ws_s[k][mq * 4] =
                    *(const float4*)&g_wq[(dbase + k) * COUT + mq * 4];
            }
            // ---- im2col gather x slab: KT x NT floats ----
            #pragma unroll
            for (int t = 0; t < 8; t++) {
                int idx = tid + t * NTHREADS;     // 0..4095
                int k   = idx >> 7;
                int p   = idx & 127;
                int d   = dbase + k;
                int c   = d / 9;
                int e   = d - c * 9;
                int e3  = e / 3;
                int dy  = e3 - 1;
                int dx  = (e - e3 * 3) - 1;
                int y   = y0 + (p >> 5) + dy;
                int x   = (p & 31) + dx;
                float v = 0.0f;
                if ((unsigned)y < 32u && (unsigned)x < 32u)
                    v = inb[(c * HH + y) * WW + x];
                xs_s[k][p] = v;
            }
            __syncthreads();

            // ---- compute: 32 k-steps, 64 FMAs each via 32 fma.rn.f32x2 ----
            #pragma unroll 8
            for (int k = 0; k < KT; k++) {
                const ulonglong2* xr =
                    (const ulonglong2*)&xs_s[k][tx * 8];
                ulonglong2 xb0 = xr[0];
                ulonglong2 xb1 = xr[1];
                unsigned long long bf[4] = {xb0.x, xb0.y, xb1.x, xb1.y};

                const float4* wr = (const float4*)&ws_s[k][ty * 8];
                float4 a0 = wr[0];
                float4 a1 = wr[1];
                float af[8] = {a0.x, a0.y, a0.z, a0.w,
                               a1.x, a1.y, a1.z, a1.w};
                #pragma unroll
                for (int i = 0; i < 8; i++) {
                    unsigned long long ad;
                    asm("mov.b64 %0, {%1, %1};"
                        : "=l"(ad) : "r"(__float_as_uint(af[i])));
                    #pragma unroll
                    for (int jp = 0; jp < 4; jp++) {
                        asm("fma.rn.f32x2 %0, %1, %2, %0;"
                            : "+l"(acc[i][jp]) : "l"(ad), "l"(bf[jp]));
                    }
                }
            }
        }

        // ---- binarize this chunk, accumulate byte-packed counts ----
        #pragma unroll
        for (int i = 0; i < 8; i++) {
            #pragma unroll
            for (int q = 0; q < 2; q++) {
                float2 s0 = *(float2*)&acc[i][q * 2];
                float2 s1 = *(float2*)&acc[i][q * 2 + 1];
                unsigned inc = (s0.x >= 0.0f ? 1u : 0u)
                             | ((s0.y >= 0.0f ? 1u : 0u) << 8)
                             | ((s1.x >= 0.0f ? 1u : 0u) << 16)
                             | ((s1.y >= 0.0f ? 1u : 0u) << 24);
                cnt[i][q] += inc;
            }
        }
    }

    // ---- coalesced store: out[b][ch][pix] ----
    float* __restrict__ ob = out + (size_t)b * (COUT * HH * WW) + pixbase;
    #pragma unroll
    for (int i = 0; i < 8; i++) {
        int ch = ty * 8 + i;
        float4 v0, v1;
        v0.x = (float)( cnt[i][0]        & 255u);
        v0.y = (float)((cnt[i][0] >>  8) & 255u);
        v0.z = (float)((cnt[i][0] >> 16) & 255u);
        v0.w = (float)((cnt[i][0] >> 24) & 255u);
        v1.x = (float)( cnt[i][1]        & 255u);
        v1.y = (float)((cnt[i][1] >>  8) & 255u);
        v1.z = (float)((cnt[i][1] >> 16) & 255u);
        v1.w = (float)((cnt[i][1] >> 24) & 255u);
        *(float4*)&ob[ch * 1024 + tx * 8]     = v0;
        *(float4*)&ob[ch * 1024 + tx * 8 + 4] = v1;
    }
}

extern "C" void kernel_launch(void* const* d_in, const int* in_sizes, int n_in,
                              void* d_out, int out_size) {
    const float* inp    = (const float*)d_in[0];  // [16,128,32,32]
    const float* weight = (const float*)d_in[1];  // [256,128,3,3]
    float* out          = (float*)d_out;          // [16,256,32,32]

    const int nw = COUT * DTOT;  // 294912

    k_init_mm<<<1, 32>>>();
    k_minmax<<<256, 256>>>(weight, nw);
    k_quant<<<(nw + 255) / 256, 256>>>(weight);
    k_onn_main<<<NPIX / NT, NTHREADS>>>(inp, out);
}